// round 14
// baseline (speedup 1.0000x reference)
#include <cuda_runtime.h>
#include <cuda_bf16.h>
#include <cuda_fp16.h>
#include <cstdint>

#define BATCHN 4096
#define SEQLEN 80
#define EMBD   100
#define UNITS  64
#define NG     256                 // 4*UNITS gates
#define PROWS  (79 * 128)          // vocab padded to m-tiles

// ---------------- device scratch (allocation-free: device globals) ----------
__device__ __nv_bfloat16 g_embbf[10000 * 128];           // emb->bf16, K padded to 128
__device__ __nv_bfloat16 g_Wt1  [256 * 128];             // W1^T bf16 [n][k], k padded
__device__ uint16_t      g_P    [(size_t)PROWS * 256];   // f16 table: emb@W1 + b1

// ---------------- helpers ---------------------------------------------------
__device__ __forceinline__ float tanhapx(float x) {
    float y; asm("tanh.approx.f32 %0, %1;" : "=f"(y) : "f"(x)); return y;
}
__device__ __forceinline__ uint32_t smem_u32(const void* p) {
    uint32_t a;
    asm("{ .reg .u64 t; cvta.to.shared.u64 t, %1; cvt.u32.u64 %0, t; }" : "=r"(a) : "l"(p));
    return a;
}
__device__ __forceinline__ uint32_t hmul2(uint32_t a, uint32_t b) {
    uint32_t d; asm("mul.rn.f16x2 %0,%1,%2;" : "=r"(d) : "r"(a), "r"(b)); return d;
}
__device__ __forceinline__ uint32_t hfma2(uint32_t a, uint32_t b, uint32_t c) {
    uint32_t d; asm("fma.rn.f16x2 %0,%1,%2,%3;" : "=r"(d) : "r"(a), "r"(b), "r"(c)); return d;
}
__device__ __forceinline__ uint32_t htanh2(uint32_t a) {
    uint32_t d; asm("tanh.approx.f16x2 %0,%1;" : "=r"(d) : "r"(a)); return d;
}
__device__ __forceinline__ uint32_t packh(float lo, float hi) {
    uint32_t d; asm("cvt.rn.f16x2.f32 %0,%1,%2;" : "=r"(d) : "f"(hi), "f"(lo)); return d;
}
__device__ __forceinline__ float2 h2tof2(uint32_t h) {
    float lo, hi;
    asm("{ .reg .b16 l,h; mov.b32 {l,h}, %2; cvt.f32.f16 %0, l; cvt.f32.f16 %1, h; }"
        : "=f"(lo), "=f"(hi) : "r"(h));
    return make_float2(lo, hi);
}
// bf16 HMMA, f32 acc (P-table GEMM only)
__device__ __forceinline__ void mma16816(float* d, const uint32_t* a, const uint32_t* b) {
    asm volatile(
        "mma.sync.aligned.m16n8k16.row.col.f32.bf16.bf16.f32 "
        "{%0,%1,%2,%3}, {%4,%5,%6,%7}, {%8,%9}, {%0,%1,%2,%3};"
        : "+f"(d[0]), "+f"(d[1]), "+f"(d[2]), "+f"(d[3])
        : "r"(a[0]), "r"(a[1]), "r"(a[2]), "r"(a[3]), "r"(b[0]), "r"(b[1]));
}
// f16 HMMA, f16 acc (scan)
__device__ __forceinline__ void mma16816hh(uint32_t* d, const uint32_t* a, const uint32_t* b) {
    asm volatile(
        "mma.sync.aligned.m16n8k16.row.col.f16.f16.f16.f16 "
        "{%0,%1}, {%2,%3,%4,%5}, {%6,%7}, {%0,%1};"
        : "+r"(d[0]), "+r"(d[1])
        : "r"(a[0]), "r"(a[1]), "r"(a[2]), "r"(a[3]), "r"(b[0]), "r"(b[1]));
}
__device__ __forceinline__ void ldmx4(uint32_t* r, uint32_t addr) {
    asm volatile("ldmatrix.sync.aligned.m8n8.x4.shared.b16 {%0,%1,%2,%3}, [%4];"
        : "=r"(r[0]), "=r"(r[1]), "=r"(r[2]), "=r"(r[3]) : "r"(addr));
}
__device__ __forceinline__ void cpa16(uint32_t dst, const void* gsrc) {
    asm volatile("{ .reg .u64 ga; cvta.to.global.u64 ga, %1; "
                 "cp.async.ca.shared.global [%0], [ga], 16; }"
                 :: "r"(dst), "l"(gsrc) : "memory");
}
#define CPA_COMMIT() asm volatile("cp.async.commit_group;" ::: "memory")
#define CPA_WAIT0()  asm volatile("cp.async.wait_group 0;" ::: "memory")
#define BARS(id, n)  asm volatile("bar.sync %0, %1;"   :: "n"(id), "n"(n) : "memory")
// runtime-id barriers (count 512)
__device__ __forceinline__ void bars_r(int id) {
    asm volatile("bar.sync %0, 512;" :: "r"(id) : "memory");
}
__device__ __forceinline__ void bara_r(int id) {
    asm volatile("bar.arrive %0, 512;" :: "r"(id) : "memory");
}

// f16x2 LSTM cell pair (R11 numerics: sigmoid via 0.5*tanh(0.5x)+0.5)
__device__ __forceinline__ uint32_t lstm_cell2h(
    uint32_t zi, uint32_t zf, uint32_t zg, uint32_t zo, uint32_t& c2)
{
    const uint32_t H05 = 0x38003800u;   // (0.5, 0.5)
    uint32_t si = hfma2(htanh2(hmul2(zi, H05)), H05, H05);
    uint32_t sf = hfma2(htanh2(hmul2(zf, H05)), H05, H05);
    uint32_t tg = htanh2(zg);
    uint32_t so = hfma2(htanh2(hmul2(zo, H05)), H05, H05);
    c2 = hfma2(sf, c2, hmul2(si, tg));
    return hmul2(so, htanh2(c2));
}

// ---------------------------------------------------------------------------
// Pre-conversion kernels
// ---------------------------------------------------------------------------
__global__ void conv_emb_kernel(const float* __restrict__ emb) {
    int idx = blockIdx.x * 256 + threadIdx.x;
    int v = idx >> 7, c = idx & 127;
    g_embbf[idx] = (c < EMBD) ? __float2bfloat16(emb[v * EMBD + c]) : __nv_bfloat16(0.f);
}
__global__ void conv_w1_kernel(const float* __restrict__ W) {
    int idx = blockIdx.x * 256 + threadIdx.x;
    int n = idx >> 7, c = idx & 127;
    g_Wt1[idx] = (c < EMBD) ? __float2bfloat16(W[c * NG + n]) : __nv_bfloat16(0.f);
}

// ---------------------------------------------------------------------------
// P-table GEMM: P[v][0:256] = emb[v]@W1 + b1 (f16 out). Grid (2, 79).
// ---------------------------------------------------------------------------
__global__ void __launch_bounds__(256, 2) gemm_P(const float* __restrict__ bias)
{
    constexpr int K = 112, SA = K + 8, KH = K / 2;
    extern __shared__ __nv_bfloat16 smbf[];
    __nv_bfloat16* Asm = smbf;
    __nv_bfloat16* Bsm = smbf + 128 * SA;

    const int tid = threadIdx.x;
    const int m0  = blockIdx.y * 128;
    const int c0  = blockIdx.x * 128;

    for (int idx = tid; idx < 128 * KH; idx += 256) {
        int row = idx / KH, kc = (idx - row * KH) * 2;
        int m = m0 + row; if (m > 9999) m = 9999;
        *(uint32_t*)&Asm[row * SA + kc] = *(const uint32_t*)&g_embbf[(size_t)m * 128 + kc];
    }
    for (int idx = tid; idx < 128 * KH; idx += 256) {
        int row = idx / KH, kc = (idx - row * KH) * 2;
        *(uint32_t*)&Bsm[row * SA + kc] = *(const uint32_t*)&g_Wt1[(size_t)(c0 + row) * 128 + kc];
    }
    __syncthreads();

    const int wid  = tid >> 5, lid = tid & 31;
    const int wrow = wid & 3, wcol = wid >> 2;
    const int g    = lid >> 2, t = lid & 3;

    const uint32_t a_base = smem_u32(Asm);
    const uint32_t b_base = smem_u32(Bsm);
    const uint32_t a_lane = (uint32_t)((wrow * 32 + (lid & 15)) * SA * 2 + (lid >> 4) * 16);
    const uint32_t b_lane = (uint32_t)((wcol * 64 + (lid >> 4) * 8 + (lid & 7)) * SA * 2 +
                                       ((lid >> 3) & 1) * 16);

    float acc[2][8][4];
    #pragma unroll
    for (int mt = 0; mt < 2; mt++)
        #pragma unroll
        for (int nt = 0; nt < 8; nt++)
            #pragma unroll
            for (int r = 0; r < 4; r++) acc[mt][nt][r] = 0.f;

    #pragma unroll
    for (int s = 0; s < K / 16; s++) {
        uint32_t af[2][4], bfr[8][2];
        #pragma unroll
        for (int mt = 0; mt < 2; mt++)
            ldmx4(af[mt], a_base + a_lane + (uint32_t)(mt * 16 * SA * 2 + s * 32));
        #pragma unroll
        for (int np = 0; np < 4; np++) {
            uint32_t bq[4];
            ldmx4(bq, b_base + b_lane + (uint32_t)(np * 16 * SA * 2 + s * 32));
            bfr[np * 2][0] = bq[0]; bfr[np * 2][1] = bq[1];
            bfr[np * 2 + 1][0] = bq[2]; bfr[np * 2 + 1][1] = bq[3];
        }
        #pragma unroll
        for (int mt = 0; mt < 2; mt++)
            #pragma unroll
            for (int nt = 0; nt < 8; nt++)
                mma16816(acc[mt][nt], af[mt], bfr[nt]);
    }

    #pragma unroll
    for (int nt = 0; nt < 8; nt++) {
        const int col = c0 + wcol * 64 + nt * 8 + t * 2;
        float2 bb = *(const float2*)&bias[col];
        #pragma unroll
        for (int mt = 0; mt < 2; mt++) {
            const int row = m0 + wrow * 32 + mt * 16 + g;
            *(uint32_t*)&g_P[(size_t)row * 256 + col] =
                packh(acc[mt][nt][0] + bb.x, acc[mt][nt][1] + bb.y);
            *(uint32_t*)&g_P[(size_t)(row + 8) * 256 + col] =
                packh(acc[mt][nt][2] + bb.x, acc[mt][nt][3] + bb.y);
        }
    }
}

// ---------------------------------------------------------------------------
// Decoupled warp-specialized scan, PER-SLOT barriers (fixes R13 deadlock).
// 128 CTAs x 512 thr, 32 rows/CTA. h1 = 3-slot ring (slot t%3).
// Ready R[s]=bar 1+s (L1 arrive, L2 sync), credit C[s]=bar 4+s (L2 arrive,
// L1 sync before overwrite, t>=3). Strict per-barrier alternation is enforced
// by the credit chain -> no token accumulation. bar7(256)=L1 internal,
// bar0(512)=final join.
// ---------------------------------------------------------------------------
#define XS_OFF  0                      // 2 x 32 x 528  = 33792 (f16 P rows)
#define H1_OFF  33792                  // 3 x 32 x 144  = 13824 (ring)
#define H2_OFF  47616                  // 2 x 32 x 144  = 9216
#define TOK_OFF 56832                  // 32 x 80 x 2   = 5120
#define SM_TOTAL 61952

__global__ void __launch_bounds__(512, 1) lstm_ws(
    const int*   __restrict__ tokens,
    const float* __restrict__ U1,
    const float* __restrict__ W2,
    const float* __restrict__ U2,
    const float* __restrict__ b2,
    const float* __restrict__ Wd,
    const float* __restrict__ bd,
    float*       __restrict__ out)
{
    extern __shared__ char sm[];
    const int tid = threadIdx.x, wid = tid >> 5, lid = tid & 31;
    const int g = lid >> 2, t4 = lid & 3;
    const int w8 = wid & 7;
    const int b0 = blockIdx.x * 32;

    uint16_t* toks = (uint16_t*)(sm + TOK_OFF);

    {   // zero h1 ring + h2 buffers
        uint32_t* z1 = (uint32_t*)(sm + H1_OFF);
        for (int i = tid; i < (13824 + 9216) / 4; i += 512) z1[i] = 0u;
    }
    for (int idx = tid; idx < 32 * SEQLEN; idx += 512)
        toks[idx] = (uint16_t)tokens[(size_t)(b0 + idx / SEQLEN) * SEQLEN + idx % SEQLEN];
    __syncthreads();

    const uint32_t xs_b = smem_u32(sm + XS_OFF);
    const uint32_t h1b  = smem_u32(sm + H1_OFF);          // ring base, slot s: +s*4608
    const uint32_t h2b0 = smem_u32(sm + H2_OFF), h2b1 = h2b0 + 4608;
    const uint32_t a_lane_h = (uint32_t)((lid & 15) * 144 + (lid >> 4) * 16);
    const int colb = (w8 * 8 + t4 * 2) * 2;

    if (wid < 8) {
        // =================== L1 producer group ===================
        auto stage_x = [&](int buf, int t) {
            const uint32_t dbase = xs_b + buf * 16896;
            #pragma unroll
            for (int i = 0; i < 4; i++) {
                int idx = tid + i * 256;       // 32 rows x 32 chunks of 16B
                int row = idx >> 5, ch = idx & 31;
                cpa16(dbase + row * 528 + ch * 16,
                      g_P + (size_t)toks[row * SEQLEN + t] * 256 + ch * 8);
            }
        };
        stage_x(0, 0);
        CPA_COMMIT();

        uint32_t bu1[4][4][2];
        #pragma unroll
        for (int gg = 0; gg < 4; gg++) {
            const int n = gg * 64 + w8 * 8 + g;
            #pragma unroll
            for (int kt = 0; kt < 4; kt++) {
                const int k0 = kt * 16 + t4 * 2;
                bu1[gg][kt][0] = packh(U1[(size_t)k0 * NG + n],       U1[(size_t)(k0 + 1) * NG + n]);
                bu1[gg][kt][1] = packh(U1[(size_t)(k0 + 8) * NG + n], U1[(size_t)(k0 + 9) * NG + n]);
            }
        }
        CPA_WAIT0();
        BARS(7, 256);                               // xs(0) visible within L1

        uint32_t c1[2][2] = {{0u, 0u}, {0u, 0u}};

        // ---- t = 0 peel: h1(0) = cell(x(0)) -> slot 0; stage x(1) ----
        stage_x(1, 1);
        CPA_COMMIT();
        {
            const char* xb = sm + XS_OFF;
            char* h1wr = sm + H1_OFF;               // slot 0
            #pragma unroll
            for (int mt = 0; mt < 2; mt++)
                #pragma unroll
                for (int rs = 0; rs < 2; rs++) {
                    const int row = mt * 16 + g + rs * 8;
                    uint32_t z0 = *(const uint32_t*)(xb + row * 528 + 0 * 128 + colb);
                    uint32_t z1v = *(const uint32_t*)(xb + row * 528 + 1 * 128 + colb);
                    uint32_t z2 = *(const uint32_t*)(xb + row * 528 + 2 * 128 + colb);
                    uint32_t z3 = *(const uint32_t*)(xb + row * 528 + 3 * 128 + colb);
                    uint32_t hv = lstm_cell2h(z0, z1v, z2, z3, c1[mt][rs]);
                    *(uint32_t*)(h1wr + row * 144 + colb) = hv;
                }
        }
        bara_r(1 + 0);                              // R[0]: h1(0) ready
        CPA_WAIT0();
        BARS(7, 256);                               // L1 internal

        int sw = 1, sr = 0;                         // write slot t%3, read slot (t-1)%3
        for (int t = 1; t < SEQLEN; ++t) {
            if (t >= 3) bars_r(4 + sw);             // C[sw]: slot free (L2 consumed t-3)
            if (t + 1 < SEQLEN) stage_x((t + 1) & 1, t + 1);
            CPA_COMMIT();

            const uint32_t h1rd = h1b + (uint32_t)(sr * 4608);
            uint32_t acc1[2][4][2];
            const char* xb = sm + XS_OFF + (t & 1) * 16896;
            #pragma unroll
            for (int mt = 0; mt < 2; mt++)
                #pragma unroll
                for (int gg = 0; gg < 4; gg++) {
                    acc1[mt][gg][0] = *(const uint32_t*)(xb + (mt * 16 + g) * 528 + gg * 128 + colb);
                    acc1[mt][gg][1] = *(const uint32_t*)(xb + (mt * 16 + g + 8) * 528 + gg * 128 + colb);
                }
            #pragma unroll
            for (int kt = 0; kt < 4; kt++) {
                uint32_t a0[4], a1[4];
                ldmx4(a0, h1rd + a_lane_h + (uint32_t)(kt * 32));
                ldmx4(a1, h1rd + a_lane_h + (uint32_t)(16 * 144 + kt * 32));
                #pragma unroll
                for (int gg = 0; gg < 4; gg++) {
                    mma16816hh(acc1[0][gg], a0, bu1[gg][kt]);
                    mma16816hh(acc1[1][gg], a1, bu1[gg][kt]);
                }
            }
            char* h1wr = sm + H1_OFF + sw * 4608;
            #pragma unroll
            for (int mt = 0; mt < 2; mt++)
                #pragma unroll
                for (int rs2 = 0; rs2 < 2; rs2++) {
                    const int row = mt * 16 + g + rs2 * 8;
                    uint32_t hv = lstm_cell2h(acc1[mt][0][rs2], acc1[mt][1][rs2],
                                              acc1[mt][2][rs2], acc1[mt][3][rs2], c1[mt][rs2]);
                    *(uint32_t*)(h1wr + row * 144 + colb) = hv;
                }
            bara_r(1 + sw);                         // R[sw]: h1(t) ready
            CPA_WAIT0();
            BARS(7, 256);                           // L1 internal
            sr = sw;
            sw = (sw == 2) ? 0 : sw + 1;
        }
        BARS(0, 512);                               // final join
    } else {
        // =================== L2 consumer group ===================
        uint32_t bw2[4][4][2], bu2[4][4][2], rb2[4];
        #pragma unroll
        for (int gg = 0; gg < 4; gg++) {
            const int n = gg * 64 + w8 * 8 + g;
            #pragma unroll
            for (int kt = 0; kt < 4; kt++) {
                const int k0 = kt * 16 + t4 * 2;
                bw2[gg][kt][0] = packh(W2[(size_t)k0 * NG + n],       W2[(size_t)(k0 + 1) * NG + n]);
                bw2[gg][kt][1] = packh(W2[(size_t)(k0 + 8) * NG + n], W2[(size_t)(k0 + 9) * NG + n]);
                bu2[gg][kt][0] = packh(U2[(size_t)k0 * NG + n],       U2[(size_t)(k0 + 1) * NG + n]);
                bu2[gg][kt][1] = packh(U2[(size_t)(k0 + 8) * NG + n], U2[(size_t)(k0 + 9) * NG + n]);
            }
            const int col = gg * 64 + w8 * 8 + t4 * 2;
            rb2[gg] = packh(b2[col], b2[col + 1]);
        }

        uint32_t c2s[2][2] = {{0u, 0u}, {0u, 0u}};
        int sr = 0;                                 // slot (t-1)%3

        for (int t = 1; t < SEQLEN; ++t) {
            bars_r(1 + sr);                         // R[sr]: wait h1(t-1); L2 rendezvous
            const uint32_t h1rd = h1b + (uint32_t)(sr * 4608);
            const uint32_t h2rd = (t & 1) ? h2b1 : h2b0;
            uint32_t acc2[2][4][2];
            #pragma unroll
            for (int mt = 0; mt < 2; mt++)
                #pragma unroll
                for (int gg = 0; gg < 4; gg++) { acc2[mt][gg][0] = rb2[gg]; acc2[mt][gg][1] = rb2[gg]; }
            #pragma unroll
            for (int kt = 0; kt < 4; kt++) {
                uint32_t a0[4], a1[4];
                ldmx4(a0, h1rd + a_lane_h + (uint32_t)(kt * 32));
                ldmx4(a1, h1rd + a_lane_h + (uint32_t)(16 * 144 + kt * 32));
                #pragma unroll
                for (int gg = 0; gg < 4; gg++) {
                    mma16816hh(acc2[0][gg], a0, bw2[gg][kt]);
                    mma16816hh(acc2[1][gg], a1, bw2[gg][kt]);
                }
            }
            #pragma unroll
            for (int kt = 0; kt < 4; kt++) {
                uint32_t a0[4], a1[4];
                ldmx4(a0, h2rd + a_lane_h + (uint32_t)(kt * 32));
                ldmx4(a1, h2rd + a_lane_h + (uint32_t)(16 * 144 + kt * 32));
                #pragma unroll
                for (int gg = 0; gg < 4; gg++) {
                    mma16816hh(acc2[0][gg], a0, bu2[gg][kt]);
                    mma16816hh(acc2[1][gg], a1, bu2[gg][kt]);
                }
            }
            char* h2wr = sm + H2_OFF + ((t & 1) ^ 1) * 4608;
            #pragma unroll
            for (int mt = 0; mt < 2; mt++)
                #pragma unroll
                for (int rs2 = 0; rs2 < 2; rs2++) {
                    const int row = mt * 16 + g + rs2 * 8;
                    uint32_t hv = lstm_cell2h(acc2[mt][0][rs2], acc2[mt][1][rs2],
                                              acc2[mt][2][rs2], acc2[mt][3][rs2], c2s[mt][rs2]);
                    *(uint32_t*)(h2wr + row * 144 + colb) = hv;
                }
            if (t <= 77) bara_r(4 + sr);            // C[sr]: slot credit back to L1
            sr = (sr == 2) ? 0 : sr + 1;
        }

        // ---- epilogue (t=80): h2(79) from h1(79) (slot sr==1), h2 buf0 ----
        bars_r(1 + sr);                             // R[1]: h1(79) ready
        {
            const uint32_t h1rd = h1b + (uint32_t)(sr * 4608);
            uint32_t acc2[2][4][2];
            #pragma unroll
            for (int mt = 0; mt < 2; mt++)
                #pragma unroll
                for (int gg = 0; gg < 4; gg++) { acc2[mt][gg][0] = rb2[gg]; acc2[mt][gg][1] = rb2[gg]; }
            #pragma unroll
            for (int kt = 0; kt < 4; kt++) {
                uint32_t a0[4], a1[4];
                ldmx4(a0, h1rd + a_lane_h + (uint32_t)(kt * 32));
                ldmx4(a1, h1rd + a_lane_h + (uint32_t)(16 * 144 + kt * 32));
                #pragma unroll
                for (int gg = 0; gg < 4; gg++) {
                    mma16816hh(acc2[0][gg], a0, bw2[gg][kt]);
                    mma16816hh(acc2[1][gg], a1, bw2[gg][kt]);
                }
            }
            #pragma unroll
            for (int kt = 0; kt < 4; kt++) {
                uint32_t a0[4], a1[4];
                ldmx4(a0, h2b0 + a_lane_h + (uint32_t)(kt * 32));
                ldmx4(a1, h2b0 + a_lane_h + (uint32_t)(16 * 144 + kt * 32));
                #pragma unroll
                for (int gg = 0; gg < 4; gg++) {
                    mma16816hh(acc2[0][gg], a0, bu2[gg][kt]);
                    mma16816hh(acc2[1][gg], a1, bu2[gg][kt]);
                }
            }
            float (*hfin)[68] = reinterpret_cast<float(*)[68]>(sm + XS_OFF);
            #pragma unroll
            for (int mt = 0; mt < 2; mt++)
                #pragma unroll
                for (int rs2 = 0; rs2 < 2; rs2++) {
                    const int row = mt * 16 + g + rs2 * 8;
                    uint32_t hv = lstm_cell2h(acc2[mt][0][rs2], acc2[mt][1][rs2],
                                              acc2[mt][2][rs2], acc2[mt][3][rs2], c2s[mt][rs2]);
                    float2 f = h2tof2(hv);
                    hfin[row][w8 * 8 + t4 * 2]     = f.x;
                    hfin[row][w8 * 8 + t4 * 2 + 1] = f.y;
                }
        }
        BARS(0, 512);                               // final join
    }

    // -------------------- dense head --------------------
    if (tid < 32) {
        float (*hfin)[68] = reinterpret_cast<float(*)[68]>(sm + XS_OFF);
        float s = bd[0];
        #pragma unroll
        for (int u = 0; u < 64; u++) s += hfin[tid][u] * Wd[u];
        out[b0 + tid] = fmaf(0.5f, tanhapx(0.5f * s), 0.5f);
    }
}

// ---------------------------------------------------------------------------
extern "C" void kernel_launch(void* const* d_in, const int* in_sizes, int n_in,
                              void* d_out, int out_size)
{
    const int*   tokens = (const int*)  d_in[0];
    const float* emb    = (const float*)d_in[1];
    const float* W1     = (const float*)d_in[2];
    const float* U1     = (const float*)d_in[3];
    const float* b1     = (const float*)d_in[4];
    const float* W2     = (const float*)d_in[5];
    const float* U2     = (const float*)d_in[6];
    const float* b2     = (const float*)d_in[7];
    const float* Wd     = (const float*)d_in[8];
    const float* bd     = (const float*)d_in[9];
    float* out = (float*)d_out;

    const int smem_gp = 2 * 128 * (112 + 8) * 2;   // 61440
    cudaFuncSetAttribute(gemm_P,  cudaFuncAttributeMaxDynamicSharedMemorySize, smem_gp);
    cudaFuncSetAttribute(lstm_ws, cudaFuncAttributeMaxDynamicSharedMemorySize, SM_TOTAL);

    conv_emb_kernel<<<10000 * 128 / 256, 256>>>(emb);
    conv_w1_kernel<<<256 * 128 / 256, 256>>>(W1);
    dim3 pgrid(2, 79);
    gemm_P<<<pgrid, 256, smem_gp>>>(b1);

    lstm_ws<<<BATCHN / 32, 512, SM_TOTAL>>>(tokens, U1, W2, U2, b2, Wd, bd, out);
}